// round 3
// baseline (speedup 1.0000x reference)
#include <cuda_runtime.h>
#include <cstdint>

// Stain normalization: out = sat(exp( log(x+1e-6) @ C - beta )),  C[c][d] = M[c][d]*gamma[d]
//
// TMA-bulk pipeline version: global<->smem moves use cp.async.bulk (async proxy,
// bypasses the L1tex register/wavefront path that capped prior rounds at ~73% DRAM).
// Compute is done in place in smem with conflict-free LDS.128/STS.128.

constexpr int TPB = 256;
constexpr int TILE_FLOATS = 6144;                 // 24 KB tile = 512 pixel-groups (4 px each)
constexpr int TILE_BYTES  = TILE_FLOATS * 4;
constexpr int GROUPS_PER_TILE = TILE_FLOATS / 12; // 512

__device__ __forceinline__ uint32_t smem_u32(const void* p) {
    uint32_t a;
    asm("{ .reg .u64 t; cvta.to.shared.u64 t, %1; cvt.u32.u64 %0, t; }"
        : "=r"(a) : "l"(p));
    return a;
}

__device__ __forceinline__ void mbar_wait_parity(uint32_t mbar, uint32_t parity) {
    asm volatile(
        "{\n\t"
        ".reg .pred P;\n\t"
        "WAIT_%=:\n\t"
        "mbarrier.try_wait.parity.shared::cta.b64 P, [%0], %1;\n\t"
        "@P bra.uni DONE_%=;\n\t"
        "bra.uni WAIT_%=;\n\t"
        "DONE_%=:\n\t"
        "}"
        :: "r"(mbar), "r"(parity) : "memory");
}

__global__ __launch_bounds__(TPB)
void stain_norm_tma_kernel(const float* __restrict__ x,
                           const float* __restrict__ M,
                           const float* __restrict__ gamma,
                           const float* __restrict__ beta,
                           float* __restrict__ out)
{
    __shared__ alignas(128) float s[TILE_FLOATS];
    __shared__ alignas(8) unsigned long long mbar;

    const float* gsrc = x   + (size_t)blockIdx.x * TILE_FLOATS;
    float*       gdst = out + (size_t)blockIdx.x * TILE_FLOATS;

    const uint32_t s_a    = smem_u32(s);
    const uint32_t mbar_a = smem_u32(&mbar);

    if (threadIdx.x == 0) {
        asm volatile("mbarrier.init.shared::cta.b64 [%0], %1;"
                     :: "r"(mbar_a), "r"(1) : "memory");
    }
    __syncthreads();

    if (threadIdx.x == 0) {
        asm volatile("mbarrier.arrive.expect_tx.shared::cta.b64 _, [%0], %1;"
                     :: "r"(mbar_a), "r"(TILE_BYTES) : "memory");
        asm volatile("cp.async.bulk.shared::cta.global.mbarrier::complete_tx::bytes "
                     "[%0], [%1], %2, [%3];"
                     :: "r"(s_a), "l"(gsrc), "r"(TILE_BYTES), "r"(mbar_a) : "memory");
    }

    // Overlap constant loads with the TMA transfer.
    float g0 = __ldg(&gamma[0]), g1 = __ldg(&gamma[1]), g2 = __ldg(&gamma[2]);
    float c00 = __ldg(&M[0]) * g0, c01 = __ldg(&M[1]) * g1, c02 = __ldg(&M[2]) * g2;
    float c10 = __ldg(&M[3]) * g0, c11 = __ldg(&M[4]) * g1, c12 = __ldg(&M[5]) * g2;
    float c20 = __ldg(&M[6]) * g0, c21 = __ldg(&M[7]) * g1, c22 = __ldg(&M[8]) * g2;
    float nb0 = -__ldg(&beta[0]), nb1 = -__ldg(&beta[1]), nb2 = -__ldg(&beta[2]);

    mbar_wait_parity(mbar_a, 0);

    // Compute in place. Thread t handles groups t and t+256; LDS.128 addresses
    // have float-stride 12 across lanes -> banks (12t mod 32) distinct within
    // each 8-lane phase -> conflict-free.
    float4* s4 = reinterpret_cast<float4*>(s);
    #pragma unroll
    for (int pass = 0; pass < 2; ++pass) {
        int g = pass * TPB + threadIdx.x;            // 0..511
        float4 va = s4[3 * g + 0];
        float4 vb = s4[3 * g + 1];
        float4 vc = s4[3 * g + 2];

        float in[12] = { va.x, va.y, va.z, va.w,
                         vb.x, vb.y, vb.z, vb.w,
                         vc.x, vc.y, vc.z, vc.w };
        float ov[12];

        #pragma unroll
        for (int p = 0; p < 4; ++p) {
            float l0 = __logf(in[3 * p + 0] + 1e-6f);
            float l1 = __logf(in[3 * p + 1] + 1e-6f);
            float l2 = __logf(in[3 * p + 2] + 1e-6f);

            float u0 = fmaf(l0, c00, fmaf(l1, c10, fmaf(l2, c20, nb0)));
            float u1 = fmaf(l0, c01, fmaf(l1, c11, fmaf(l2, c21, nb1)));
            float u2 = fmaf(l0, c02, fmaf(l1, c12, fmaf(l2, c22, nb2)));

            ov[3 * p + 0] = __saturatef(__expf(u0));
            ov[3 * p + 1] = __saturatef(__expf(u1));
            ov[3 * p + 2] = __saturatef(__expf(u2));
        }

        s4[3 * g + 0] = make_float4(ov[0], ov[1], ov[2],  ov[3]);
        s4[3 * g + 1] = make_float4(ov[4], ov[5], ov[6],  ov[7]);
        s4[3 * g + 2] = make_float4(ov[8], ov[9], ov[10], ov[11]);
    }
    __syncthreads();

    if (threadIdx.x == 0) {
        asm volatile("fence.proxy.async.shared::cta;" ::: "memory");
        asm volatile("cp.async.bulk.global.shared::cta.bulk_group [%0], [%1], %2;"
                     :: "l"(gdst), "r"(s_a), "r"(TILE_BYTES) : "memory");
        asm volatile("cp.async.bulk.commit_group;" ::: "memory");
        asm volatile("cp.async.bulk.wait_group 0;" ::: "memory");
    }
}

// Scalar tail for leftover elements (none for the bench shape; kept for robustness).
__global__ void stain_norm_tail_kernel(const float* __restrict__ x,
                                       const float* __restrict__ M,
                                       const float* __restrict__ gamma,
                                       const float* __restrict__ beta,
                                       float* __restrict__ out,
                                       int start_elem, int n_elem)
{
    int e = start_elem + blockIdx.x * blockDim.x + threadIdx.x;
    if (e >= n_elem) return;
    int pix = e / 3;
    int d = e - pix * 3;
    float l0 = __logf(x[pix * 3 + 0] + 1e-6f);
    float l1 = __logf(x[pix * 3 + 1] + 1e-6f);
    float l2 = __logf(x[pix * 3 + 2] + 1e-6f);
    float gd = __ldg(&gamma[d]);
    float u = fmaf(l0, __ldg(&M[0 * 3 + d]) * gd,
             fmaf(l1, __ldg(&M[1 * 3 + d]) * gd,
             fmaf(l2, __ldg(&M[2 * 3 + d]) * gd, -__ldg(&beta[d]))));
    out[e] = __saturatef(__expf(u));
}

extern "C" void kernel_launch(void* const* d_in, const int* in_sizes, int n_in,
                              void* d_out, int out_size)
{
    const float* x     = (const float*)d_in[0];
    const float* M     = (const float*)d_in[1];
    const float* gamma = (const float*)d_in[2];
    const float* beta  = (const float*)d_in[3];
    float* out = (float*)d_out;

    int n_elem  = in_sizes[0];                 // total floats
    int n_tiles = n_elem / TILE_FLOATS;        // full 24 KB tiles

    if (n_tiles > 0) {
        stain_norm_tma_kernel<<<n_tiles, TPB>>>(x, M, gamma, beta, out);
    }

    int done = n_tiles * TILE_FLOATS;          // multiple of 12 -> pixel-aligned
    int rem = n_elem - done;
    if (rem > 0) {
        int threads = 256;
        int blocks = (rem + threads - 1) / threads;
        stain_norm_tail_kernel<<<blocks, threads>>>(x, M, gamma, beta, out, done, n_elem);
    }
}